// round 16
// baseline (speedup 1.0000x reference)
#include <cuda_runtime.h>
#include <cuda_fp16.h>
#include <math.h>
#include <stdint.h>
#include <string.h>

#define B_   2
#define T_   4096
#define C_   768
#define NH_  12
#define HD_  64
#define C3_  (3*C_)
#define M_   (B_*T_)       // 8192

// q pre-scale: 1/sqrt(64) * log2(e)
#define QSCALE 0.1803368801111204f

typedef unsigned long long ull;

// Scratch (allocation-free: __device__ globals)
__device__ __half g_qkvs[(size_t)B_*3*NH_*T_*HD_];   // 37.7 MB fp16 qkv (per-head)
__device__ __half g_yh[(size_t)M_*C_];               // 12.6 MB fp16 y
__device__ __half g_xh[(size_t)M_*C_];               // 12.6 MB fp16 x
__device__ __half g_b1h[(size_t)C3_*C_];             //  3.5 MB w_attn^T fp16
__device__ __half g_b2h[(size_t)C_*C_];              //  1.2 MB w_proj^T fp16

__device__ __forceinline__ uint32_t smem_u32(const void* p) {
    uint32_t a;
    asm("{ .reg .u64 t; cvta.to.shared.u64 t, %1; cvt.u32.u64 %0, t; }" : "=r"(a) : "l"(p));
    return a;
}

// ---- packed f16x2 ALU ops ---------------------------------------------------
__device__ __forceinline__ uint32_t hadd2_(uint32_t a, uint32_t b) {
    uint32_t r; asm("add.f16x2 %0, %1, %2;" : "=r"(r) : "r"(a), "r"(b)); return r;
}
__device__ __forceinline__ uint32_t hex2(uint32_t a) {
    uint32_t r; asm("ex2.approx.f16x2 %0, %1;" : "=r"(r) : "r"(a)); return r;
}

// ---- cp.async helpers ------------------------------------------------------
__device__ __forceinline__ void cpa16(uint32_t dst, const void* src) {
    asm volatile("cp.async.cg.shared.global [%0], [%1], 16;" :: "r"(dst), "l"(src));
}
#define CP_COMMIT() asm volatile("cp.async.commit_group;" ::: "memory")
#define CP_WAIT0()  asm volatile("cp.async.wait_group 0;" ::: "memory")

// ---- warp-level tensor core ops --------------------------------------------
__device__ __forceinline__ void ldsm4(uint32_t& r0, uint32_t& r1,
                                      uint32_t& r2, uint32_t& r3, uint32_t addr) {
    asm volatile("ldmatrix.sync.aligned.m8n8.x4.shared.b16 {%0,%1,%2,%3}, [%4];"
                 : "=r"(r0), "=r"(r1), "=r"(r2), "=r"(r3) : "r"(addr));
}
__device__ __forceinline__ void ldsm4t(uint32_t& r0, uint32_t& r1,
                                       uint32_t& r2, uint32_t& r3, uint32_t addr) {
    asm volatile("ldmatrix.sync.aligned.m8n8.x4.trans.shared.b16 {%0,%1,%2,%3}, [%4];"
                 : "=r"(r0), "=r"(r1), "=r"(r2), "=r"(r3) : "r"(addr));
}
// fp16 mma, fp32 accum
__device__ __forceinline__ void mma_hf(float* c, const uint32_t* a,
                                       uint32_t b0, uint32_t b1) {
    asm volatile(
        "mma.sync.aligned.m16n8k16.row.col.f32.f16.f16.f32 "
        "{%0,%1,%2,%3}, {%4,%5,%6,%7}, {%8,%9}, {%0,%1,%2,%3};"
        : "+f"(c[0]), "+f"(c[1]), "+f"(c[2]), "+f"(c[3])
        : "r"(a[0]), "r"(a[1]), "r"(a[2]), "r"(a[3]), "r"(b0), "r"(b1));
}
// fp16 mma, fp16 accum
__device__ __forceinline__ void mma_h16(uint32_t* c, const uint32_t* a,
                                        uint32_t b0, uint32_t b1) {
    asm volatile(
        "mma.sync.aligned.m16n8k16.row.col.f16.f16.f16.f16 "
        "{%0,%1}, {%2,%3,%4,%5}, {%6,%7}, {%0,%1};"
        : "+r"(c[0]), "+r"(c[1])
        : "r"(a[0]), "r"(a[1]), "r"(a[2]), "r"(a[3]), "r"(b0), "r"(b1));
}

// pack two fp32 into fp16x2 (p0 low, p1 high)
__device__ __forceinline__ uint32_t h2pack(float p0, float p1) {
    uint32_t r;
    asm("cvt.rn.f16x2.f32 %0, %1, %2;" : "=r"(r) : "f"(p1), "f"(p0));
    return r;
}

// ---------------------------------------------------------------------------
// Fused prep: x -> g_xh (fp16), w_attn -> g_b1h (W^T fp16), w_proj -> g_b2h.
// Range-dispatched on global index (one launch).
// ---------------------------------------------------------------------------
#define PREP_X4   (M_ * C_ / 4)                 // 1,572,864 float4 items
#define PREP_W1   (C3_ * (C_ / 4))              //   442,368 items
#define PREP_W2   (C_ * (C_ / 4))               //   147,456 items
#define PREP_TOTAL (PREP_X4 + PREP_W1 + PREP_W2)

__global__ void prep_all(const float* __restrict__ x,
                         const float* __restrict__ w1,
                         const float* __restrict__ w2)
{
    int i = blockIdx.x * blockDim.x + threadIdx.x;
    if (i < PREP_X4) {
        float4 v = reinterpret_cast<const float4*>(x)[i];
        uint2 o;
        o.x = h2pack(v.x, v.y);
        o.y = h2pack(v.z, v.w);
        reinterpret_cast<uint2*>(g_xh)[i] = o;
        return;
    }
    i -= PREP_X4;
    if (i < PREP_W1) {
        int k4 = i / C3_, n = i % C3_;
        uint32_t p01 = h2pack(w1[(size_t)(k4 * 4 + 0) * C3_ + n],
                              w1[(size_t)(k4 * 4 + 1) * C3_ + n]);
        uint32_t p23 = h2pack(w1[(size_t)(k4 * 4 + 2) * C3_ + n],
                              w1[(size_t)(k4 * 4 + 3) * C3_ + n]);
        *reinterpret_cast<uint2*>(&g_b1h[(size_t)n * C_ + k4 * 4]) =
            make_uint2(p01, p23);
        return;
    }
    i -= PREP_W1;
    if (i < PREP_W2) {
        int k4 = i / C_, n = i % C_;
        uint32_t p01 = h2pack(w2[(size_t)(k4 * 4 + 0) * C_ + n],
                              w2[(size_t)(k4 * 4 + 1) * C_ + n]);
        uint32_t p23 = h2pack(w2[(size_t)(k4 * 4 + 2) * C_ + n],
                              w2[(size_t)(k4 * 4 + 3) * C_ + n]);
        *reinterpret_cast<uint2*>(&g_b2h[(size_t)n * C_ + k4 * 4]) =
            make_uint2(p01, p23);
    }
}

// ---------------------------------------------------------------------------
// fp16 mma.sync GEMM v2: CTA 128x128, 4 warps of 64x64 (zero fragment
// redundancy), 2-stage cp.async (64KB smem -> 2 CTAs/SM), 1 sync per chunk.
// ---------------------------------------------------------------------------
#define G_SMEM_TOTAL 65536

struct GemmCore {
    float acc[4][8][4];
    int wm, wn, lane;
};

__device__ __forceinline__ void gemm_issue_chunk(
    uint32_t sbase, const __half* Ah, const __half* Bh,
    int m0, int n0, int K, int ch, int r, int c8)
{
    const uint32_t bofs = (uint32_t)((ch & 1) * 32768);
    const int kb = ch * 64;
    #pragma unroll
    for (int p = 0; p < 8; p++) {
        int rr = r + p * 16;
        uint32_t bo = (uint32_t)(rr * 128 + c8 * 16);
        uint32_t sw = bo ^ ((bo >> 3) & 0x70);
        cpa16(sbase + bofs + sw,         &Ah[(size_t)(m0 + rr) * K + kb + c8 * 8]);
        cpa16(sbase + bofs + 16384 + sw, &Bh[(size_t)(n0 + rr) * K + kb + c8 * 8]);
    }
    CP_COMMIT();
}

__device__ __forceinline__ void gemm_mainloop(
    GemmCore& gc, char* smem, const __half* Ah, const __half* Bh,
    int m0, int n0, int K, int tid)
{
    const uint32_t sbase = smem_u32(smem);
    const int lane = gc.lane;
    const int r  = tid >> 3;      // 0..15
    const int c8 = tid & 7;
    const int lrow = (lane & 7) + ((lane >> 3) & 1) * 8;
    const int lkc  = (lane >> 4);

    #pragma unroll
    for (int t = 0; t < 4; t++)
        #pragma unroll
        for (int g = 0; g < 8; g++)
            #pragma unroll
            for (int e = 0; e < 4; e++) gc.acc[t][g][e] = 0.f;

    const int nch = K / 64;

    gemm_issue_chunk(sbase, Ah, Bh, m0, n0, K, 0, r, c8);

    for (int ch = 0; ch < nch; ch++) {
        CP_WAIT0();
        __syncthreads();   // chunk ch visible; compute(ch-1) done in all warps
        if (ch + 1 < nch)
            gemm_issue_chunk(sbase, Ah, Bh, m0, n0, K, ch + 1, r, c8);

        const uint32_t sA = sbase + (uint32_t)((ch & 1) * 32768);
        const uint32_t sB = sA + 16384;

        #pragma unroll
        for (int ks = 0; ks < 4; ks++) {
            const int cc = ks * 2 + lkc;
            uint32_t a[4][4];
            #pragma unroll
            for (int t = 0; t < 4; t++) {
                int row = gc.wm * 64 + t * 16 + lrow;
                uint32_t bo = (uint32_t)(row * 128 + cc * 16);
                uint32_t sw = bo ^ ((bo >> 3) & 0x70);
                ldsm4(a[t][0], a[t][1], a[t][2], a[t][3], sA + sw);
            }
            uint32_t bf[4][4];
            #pragma unroll
            for (int g4 = 0; g4 < 4; g4++) {
                int row = gc.wn * 64 + g4 * 16 + lrow;
                uint32_t bo = (uint32_t)(row * 128 + cc * 16);
                uint32_t sw = bo ^ ((bo >> 3) & 0x70);
                ldsm4(bf[g4][0], bf[g4][1], bf[g4][2], bf[g4][3], sB + sw);
            }
            #pragma unroll
            for (int g4 = 0; g4 < 4; g4++) {
                #pragma unroll
                for (int t = 0; t < 4; t++) {
                    mma_hf(gc.acc[t][g4 * 2 + 0], a[t], bf[g4][0], bf[g4][2]);
                    mma_hf(gc.acc[t][g4 * 2 + 1], a[t], bf[g4][1], bf[g4][3]);
                }
            }
        }
    }
}

// GEMM2: out = y @ w_proj + bias, fp32 output
__global__ __launch_bounds__(128) void mma_gemm_out(
    const __half* __restrict__ Ah, const __half* __restrict__ Bh,
    const float* __restrict__ bias, float* __restrict__ Cm, int N)
{
    extern __shared__ char smem[];
    const int tid = threadIdx.x;
    GemmCore gc; gc.wm = (tid >> 5) & 1; gc.wn = tid >> 6; gc.lane = tid & 31;
    const int n0 = blockIdx.x * 128;
    const int m0 = blockIdx.y * 128;
    gemm_mainloop(gc, smem, Ah, Bh, m0, n0, C_, tid);

    const int crow = gc.lane >> 2;
    const int ccol = (gc.lane & 3) * 2;
    #pragma unroll
    for (int t = 0; t < 4; t++) {
        #pragma unroll
        for (int g = 0; g < 8; g++) {
            int row = m0 + gc.wm * 64 + t * 16 + crow;
            int col = n0 + gc.wn * 64 + g * 8 + ccol;
            float2 bv = *reinterpret_cast<const float2*>(&bias[col]);
            float2 o0, o1;
            o0.x = gc.acc[t][g][0] + bv.x; o0.y = gc.acc[t][g][1] + bv.y;
            o1.x = gc.acc[t][g][2] + bv.x; o1.y = gc.acc[t][g][3] + bv.y;
            *reinterpret_cast<float2*>(&Cm[(size_t)row * N + col]) = o0;
            *reinterpret_cast<float2*>(&Cm[(size_t)(row + 8) * N + col]) = o1;
        }
    }
}

// GEMM1: writes fp16 qkv per-head (q pre-scaled by 0.125*log2e)
__global__ __launch_bounds__(128) void mma_gemm_qkv(
    const __half* __restrict__ Ah, const __half* __restrict__ Bh,
    const float* __restrict__ bias)
{
    extern __shared__ char smem[];
    const int tid = threadIdx.x;
    GemmCore gc; gc.wm = (tid >> 5) & 1; gc.wn = tid >> 6; gc.lane = tid & 31;
    const int n0 = blockIdx.x * 128;
    const int m0 = blockIdx.y * 128;
    gemm_mainloop(gc, smem, Ah, Bh, m0, n0, C_, tid);

    const int crow = gc.lane >> 2;
    const int ccol = (gc.lane & 3) * 2;
    #pragma unroll
    for (int t = 0; t < 4; t++) {
        #pragma unroll
        for (int g = 0; g < 8; g++) {
            int row = m0 + gc.wm * 64 + t * 16 + crow;
            int col = n0 + gc.wn * 64 + g * 8 + ccol;
            int which = col / 768, hh = (col % 768) / 64, dd = col % 64;
            int bb = row >> 12, tt = row & 4095;
            float2 bv = *reinterpret_cast<const float2*>(&bias[col]);
            float sc_ = (which == 0) ? QSCALE : 1.f;
            float v0 = (gc.acc[t][g][0] + bv.x) * sc_;
            float v1 = (gc.acc[t][g][1] + bv.y) * sc_;
            float v2 = (gc.acc[t][g][2] + bv.x) * sc_;
            float v3 = (gc.acc[t][g][3] + bv.y) * sc_;
            size_t base = (((size_t)bb * 3 + which) * NH_ + hh) * (size_t)T_ * HD_
                        + (size_t)tt * HD_ + dd;
            *reinterpret_cast<uint32_t*>(&g_qkvs[base]) = h2pack(v0, v1);
            *reinterpret_cast<uint32_t*>(&g_qkvs[base + (size_t)8 * HD_]) = h2pack(v2, v3);
        }
    }
}

// ---------------------------------------------------------------------------
// Flash attention v12 (unchanged from R15): f16-accum S, no-max softmax,
// row-sum via ones-column MMA, packed -inf causal mask.
// 4 warps x 32q, 128 q-rows/CTA. smem 48KB.
// ---------------------------------------------------------------------------
#define FL_SMEM_BYTES 49152
#define FQ_OFF 32768

__global__ __launch_bounds__(128, 3) void flash_kernel()
{
    extern __shared__ char fsm[];
    const uint32_t sb = smem_u32(fsm);

    const int tid  = threadIdx.x;
    const int w    = tid >> 5;
    const int lane = tid & 31;
    const int qt   = (gridDim.x - 1) - blockIdx.x;   // heavy tiles first
    const int h    = blockIdx.y;
    const int b    = blockIdx.z;
    const int q0   = qt * 128;

    const int lrow = (lane & 7) + ((lane >> 3) & 1) * 8;
    const int lkc  = lane >> 4;

    // ones B-fragment for row-sum MMA: col 0 only (lanes 0-3), all k = 1.0
    const uint32_t vb1 = (lane < 4) ? 0x3C003C00u : 0u;

    // K/V cp.async: 2 tiles (K,V), 64 threads each
    const int tt  = tid >> 6;            // 0=K, 1=V
    const int ll  = tid & 63;
    const int kc8 = ll & 7;
    const int kr8 = ll >> 3;             // 0..7
    const __half* kvsrc = g_qkvs +
        (((size_t)b * 3 + 1 + tt) * NH_ + h) * (size_t)T_ * HD_;
    const uint32_t kvdst = sb + tt * 8192;

    const int ktmax = 2 * qt + 2;

    // prologue: kt=0 -> buf0
    #pragma unroll
    for (int p = 0; p < 8; p++) {
        int rr = p * 8 + kr8;
        uint32_t sw = (uint32_t)(rr * 128 + ((kc8 ^ (rr & 7)) * 16));
        cpa16(kvdst + sw, &kvsrc[(size_t)rr * HD_ + kc8 * 8]);
    }
    CP_COMMIT();

    // stage Q (fp16, pre-scaled) into persistent region
    {
        const int c8  = tid & 7;
        const int r16 = tid >> 3;        // 0..15
        const __half* qsrc = g_qkvs +
            (((size_t)b * 3 + 0) * NH_ + h) * (size_t)T_ * HD_;
        #pragma unroll
        for (int p = 0; p < 8; p++) {
            int rr = p * 16 + r16;
            uint32_t sw = (uint32_t)(rr * 128 + ((c8 ^ (rr & 7)) * 16));
            *reinterpret_cast<float4*>(fsm + FQ_OFF + sw) =
                *reinterpret_cast<const float4*>(&qsrc[(size_t)(q0 + rr) * HD_ + c8 * 8]);
        }
    }
    __syncthreads();

    // preload Q fragments: qf[t][ks]
    uint32_t qf[2][4][4];
    #pragma unroll
    for (int t = 0; t < 2; t++) {
        #pragma unroll
        for (int ks = 0; ks < 4; ks++) {
            int row = w * 32 + t * 16 + lrow;
            int cc = ks * 2 + lkc;
            uint32_t sw = (uint32_t)(FQ_OFF + row * 128 + ((cc ^ (row & 7)) * 16));
            uint32_t* q = qf[t][ks];
            ldsm4(q[0], q[1], q[2], q[3], sb + sw);
        }
    }

    float oc[2][8][4];
    float ol[2][4];   // l accumulators (col 0 of ones-MMA)
    #pragma unroll
    for (int t = 0; t < 2; t++) {
        #pragma unroll
        for (int g = 0; g < 8; g++)
            #pragma unroll
            for (int e = 0; e < 4; e++) oc[t][g][e] = 0.f;
        #pragma unroll
        for (int e = 0; e < 4; e++) ol[t][e] = 0.f;
    }

    for (int kt = 0; kt < ktmax; kt++) {
        CP_WAIT0();
        __syncthreads();   // tile kt visible; compute(kt-1) done in all warps
        if (kt + 1 < ktmax) {
            const uint32_t bofs = (uint32_t)(((kt + 1) & 1) * 16384);
            #pragma unroll
            for (int p = 0; p < 8; p++) {
                int rr = p * 8 + kr8;
                uint32_t sw = (uint32_t)(rr * 128 + ((kc8 ^ (rr & 7)) * 16));
                cpa16(kvdst + bofs + sw,
                      &kvsrc[(size_t)((kt + 1) * 64 + rr) * HD_ + kc8 * 8]);
            }
            CP_COMMIT();
        }

        const uint32_t bb_ = sb + (uint32_t)((kt & 1) * 16384);

        if (kt * 64 <= q0 + w * 32 + 31) {
            // ---- S = Q K^T (fp16 accum; C-frags are packed f16x2) ----
            uint32_t s16[2][8][2];
            #pragma unroll
            for (int t = 0; t < 2; t++)
                #pragma unroll
                for (int g = 0; g < 8; g++) {
                    s16[t][g][0] = 0u; s16[t][g][1] = 0u;
                }

            #pragma unroll
            for (int ks = 0; ks < 4; ks++) {
                const int cc = ks * 2 + lkc;
                #pragma unroll
                for (int g4 = 0; g4 < 4; g4++) {
                    int row = g4 * 16 + lrow;
                    uint32_t swz = (uint32_t)(row * 128 + ((cc ^ (row & 7)) * 16));
                    uint32_t b0, b1, b2, b3;
                    ldsm4(b0, b1, b2, b3, bb_ + swz);   // K
                    mma_h16(s16[0][2 * g4 + 0], qf[0][ks], b0, b2);
                    mma_h16(s16[0][2 * g4 + 1], qf[0][ks], b1, b3);
                    mma_h16(s16[1][2 * g4 + 0], qf[1][ks], b0, b2);
                    mma_h16(s16[1][2 * g4 + 1], qf[1][ks], b1, b3);
                }
            }

            // ---- causal mask (packed -inf adds, diagonal tiles only) ----
            if (kt * 64 + 63 > q0 + w * 32) {
                #pragma unroll
                for (int t = 0; t < 2; t++) {
                    int gr0 = q0 + w * 32 + t * 16 + (lane >> 2);
                    int gr1 = gr0 + 8;
                    #pragma unroll
                    for (int g = 0; g < 8; g++) {
                        int gc0 = kt * 64 + g * 8 + 2 * (lane & 3);
                        int gc1 = gc0 + 1;
                        uint32_t m0 = h2pack(gc0 > gr0 ? -INFINITY : 0.f,
                                             gc1 > gr0 ? -INFINITY : 0.f);
                        uint32_t m1 = h2pack(gc0 > gr1 ? -INFINITY : 0.f,
                                             gc1 > gr1 ? -INFINITY : 0.f);
                        s16[t][g][0] = hadd2_(s16[t][g][0], m0);
                        s16[t][g][1] = hadd2_(s16[t][g][1], m1);
                    }
                }
            }

            // ---- P = exp2(S) in place (packed) ----
            #pragma unroll
            for (int t = 0; t < 2; t++)
                #pragma unroll
                for (int g = 0; g < 8; g++) {
                    s16[t][g][0] = hex2(s16[t][g][0]);
                    s16[t][g][1] = hex2(s16[t][g][1]);
                }

            // ---- O += P V, l += P 1 (all on tensor pipe) ----
            #pragma unroll
            for (int j = 0; j < 4; j++) {
                uint32_t ph[2][4];
                #pragma unroll
                for (int t = 0; t < 2; t++) {
                    ph[t][0] = s16[t][2 * j][0];
                    ph[t][1] = s16[t][2 * j][1];
                    ph[t][2] = s16[t][2 * j + 1][0];
                    ph[t][3] = s16[t][2 * j + 1][1];
                }
                mma_hf(ol[0], ph[0], vb1, vb1);   // row-sum
                mma_hf(ol[1], ph[1], vb1, vb1);
                #pragma unroll
                for (int g4 = 0; g4 < 4; g4++) {
                    int row = j * 16 + lrow;
                    int cc = g4 * 2 + lkc;
                    uint32_t swz = (uint32_t)(row * 128 + ((cc ^ (row & 7)) * 16));
                    uint32_t v0, v1, v2, v3;
                    ldsm4t(v0, v1, v2, v3, bb_ + 8192 + swz);   // V
                    mma_hf(oc[0][2 * g4 + 0], ph[0], v0, v1);
                    mma_hf(oc[0][2 * g4 + 1], ph[0], v2, v3);
                    mma_hf(oc[1][2 * g4 + 0], ph[1], v0, v1);
                    mma_hf(oc[1][2 * g4 + 1], ph[1], v2, v3);
                }
            }
        }
    }

    // ---- epilogue: O / l -> fp16 rows of g_yh (l lives in quad lane 0) ----
    #pragma unroll
    for (int t = 0; t < 2; t++) {
        float l0 = __shfl_sync(0xffffffffu, ol[t][0], lane & ~3);
        float l1 = __shfl_sync(0xffffffffu, ol[t][2], lane & ~3);
        float inv0 = 1.f / l0;
        float inv1 = 1.f / l1;
        #pragma unroll
        for (int g = 0; g < 8; g++) {
            int row = q0 + w * 32 + t * 16 + (lane >> 2);
            int d0  = g * 8 + 2 * (lane & 3);
            size_t base0 = (size_t)(b * T_ + row) * C_ + h * HD_ + d0;
            *reinterpret_cast<uint32_t*>(&g_yh[base0]) =
                h2pack(oc[t][g][0] * inv0, oc[t][g][1] * inv0);
            *reinterpret_cast<uint32_t*>(&g_yh[base0 + (size_t)8 * C_]) =
                h2pack(oc[t][g][2] * inv1, oc[t][g][3] * inv1);
        }
    }
}

// ---------------------------------------------------------------------------
extern "C" void kernel_launch(void* const* d_in, const int* in_sizes, int n_in,
                              void* d_out, int out_size)
{
    const float* x      = (const float*)d_in[0];
    const float* w_attn = (const float*)d_in[1];
    const float* b_attn = (const float*)d_in[2];
    const float* w_proj = (const float*)d_in[3];
    const float* b_proj = (const float*)d_in[4];
    float* out = (float*)d_out;

    __half *xh = nullptr, *b1h = nullptr, *b2h = nullptr, *yh = nullptr;
    cudaGetSymbolAddress((void**)&xh,  g_xh);
    cudaGetSymbolAddress((void**)&b1h, g_b1h);
    cudaGetSymbolAddress((void**)&b2h, g_b2h);
    cudaGetSymbolAddress((void**)&yh,  g_yh);

    cudaFuncSetAttribute(flash_kernel,
                         cudaFuncAttributeMaxDynamicSharedMemorySize, FL_SMEM_BYTES);
    cudaFuncSetAttribute(mma_gemm_out,
                         cudaFuncAttributeMaxDynamicSharedMemorySize, G_SMEM_TOTAL);
    cudaFuncSetAttribute(mma_gemm_qkv,
                         cudaFuncAttributeMaxDynamicSharedMemorySize, G_SMEM_TOTAL);

    // 0) fused prep (one launch)
    prep_all<<<(PREP_TOTAL + 255) / 256, 256>>>(x, w_attn, w_proj);

    // 1) qkv = x @ w_attn + b_attn -> fp16 q/k/v (q scaled by 0.125*log2e)
    mma_gemm_qkv<<<dim3(C3_ / 128, M_ / 128), 128, G_SMEM_TOTAL>>>(
        xh, b1h, b_attn);

    // 2) flash attention -> g_yh
    flash_kernel<<<dim3(T_ / 128, NH_, B_), 128, FL_SMEM_BYTES>>>();

    // 3) out = y @ w_proj + b_proj
    mma_gemm_out<<<dim3(C_ / 128, M_ / 128), 128, G_SMEM_TOTAL>>>(
        yh, b2h, b_proj, out, C_);
}

// round 17
// speedup vs baseline: 1.0476x; 1.0476x over previous
#include <cuda_runtime.h>
#include <cuda_fp16.h>
#include <math.h>
#include <stdint.h>
#include <string.h>

#define B_   2
#define T_   4096
#define C_   768
#define NH_  12
#define HD_  64
#define C3_  (3*C_)
#define M_   (B_*T_)       // 8192

// q pre-scale: 1/sqrt(64) * log2(e)
#define QSCALE 0.1803368801111204f

typedef unsigned long long ull;

// Scratch (allocation-free: __device__ globals)
__device__ __half g_qkvs[(size_t)B_*3*NH_*T_*HD_];   // 37.7 MB fp16 qkv (per-head)
__device__ __half g_yh[(size_t)M_*C_];               // 12.6 MB fp16 y
__device__ __half g_xh[(size_t)M_*C_];               // 12.6 MB fp16 x
__device__ __half g_b1h[(size_t)C3_*C_];             //  3.5 MB w_attn^T fp16
__device__ __half g_b2h[(size_t)C_*C_];              //  1.2 MB w_proj^T fp16

__device__ __forceinline__ uint32_t smem_u32(const void* p) {
    uint32_t a;
    asm("{ .reg .u64 t; cvta.to.shared.u64 t, %1; cvt.u32.u64 %0, t; }" : "=r"(a) : "l"(p));
    return a;
}

// ---- packed f16x2 ALU ops ---------------------------------------------------
__device__ __forceinline__ uint32_t hadd2_(uint32_t a, uint32_t b) {
    uint32_t r; asm("add.f16x2 %0, %1, %2;" : "=r"(r) : "r"(a), "r"(b)); return r;
}
__device__ __forceinline__ uint32_t hex2(uint32_t a) {
    uint32_t r; asm("ex2.approx.f16x2 %0, %1;" : "=r"(r) : "r"(a)); return r;
}

// ---- cp.async helpers ------------------------------------------------------
__device__ __forceinline__ void cpa16(uint32_t dst, const void* src) {
    asm volatile("cp.async.cg.shared.global [%0], [%1], 16;" :: "r"(dst), "l"(src));
}
#define CP_COMMIT() asm volatile("cp.async.commit_group;" ::: "memory")
#define CP_WAIT1()  asm volatile("cp.async.wait_group 1;" ::: "memory")
#define CP_WAIT0()  asm volatile("cp.async.wait_group 0;" ::: "memory")

// ---- warp-level tensor core ops --------------------------------------------
__device__ __forceinline__ void ldsm4(uint32_t& r0, uint32_t& r1,
                                      uint32_t& r2, uint32_t& r3, uint32_t addr) {
    asm volatile("ldmatrix.sync.aligned.m8n8.x4.shared.b16 {%0,%1,%2,%3}, [%4];"
                 : "=r"(r0), "=r"(r1), "=r"(r2), "=r"(r3) : "r"(addr));
}
__device__ __forceinline__ void ldsm4t(uint32_t& r0, uint32_t& r1,
                                       uint32_t& r2, uint32_t& r3, uint32_t addr) {
    asm volatile("ldmatrix.sync.aligned.m8n8.x4.trans.shared.b16 {%0,%1,%2,%3}, [%4];"
                 : "=r"(r0), "=r"(r1), "=r"(r2), "=r"(r3) : "r"(addr));
}
// fp16 mma, fp32 accum
__device__ __forceinline__ void mma_hf(float* c, const uint32_t* a,
                                       uint32_t b0, uint32_t b1) {
    asm volatile(
        "mma.sync.aligned.m16n8k16.row.col.f32.f16.f16.f32 "
        "{%0,%1,%2,%3}, {%4,%5,%6,%7}, {%8,%9}, {%0,%1,%2,%3};"
        : "+f"(c[0]), "+f"(c[1]), "+f"(c[2]), "+f"(c[3])
        : "r"(a[0]), "r"(a[1]), "r"(a[2]), "r"(a[3]), "r"(b0), "r"(b1));
}
// fp16 mma, fp16 accum
__device__ __forceinline__ void mma_h16(uint32_t* c, const uint32_t* a,
                                        uint32_t b0, uint32_t b1) {
    asm volatile(
        "mma.sync.aligned.m16n8k16.row.col.f16.f16.f16.f16 "
        "{%0,%1}, {%2,%3,%4,%5}, {%6,%7}, {%0,%1};"
        : "+r"(c[0]), "+r"(c[1])
        : "r"(a[0]), "r"(a[1]), "r"(a[2]), "r"(a[3]), "r"(b0), "r"(b1));
}

// pack two fp32 into fp16x2 (p0 low, p1 high)
__device__ __forceinline__ uint32_t h2pack(float p0, float p1) {
    uint32_t r;
    asm("cvt.rn.f16x2.f32 %0, %1, %2;" : "=r"(r) : "f"(p1), "f"(p0));
    return r;
}

// ---------------------------------------------------------------------------
// Fused prep: x -> g_xh (fp16), w_attn -> g_b1h (W^T fp16), w_proj -> g_b2h.
// ---------------------------------------------------------------------------
#define PREP_X4   (M_ * C_ / 4)
#define PREP_W1   (C3_ * (C_ / 4))
#define PREP_W2   (C_ * (C_ / 4))
#define PREP_TOTAL (PREP_X4 + PREP_W1 + PREP_W2)

__global__ void prep_all(const float* __restrict__ x,
                         const float* __restrict__ w1,
                         const float* __restrict__ w2)
{
    int i = blockIdx.x * blockDim.x + threadIdx.x;
    if (i < PREP_X4) {
        float4 v = reinterpret_cast<const float4*>(x)[i];
        uint2 o;
        o.x = h2pack(v.x, v.y);
        o.y = h2pack(v.z, v.w);
        reinterpret_cast<uint2*>(g_xh)[i] = o;
        return;
    }
    i -= PREP_X4;
    if (i < PREP_W1) {
        int k4 = i / C3_, n = i % C3_;
        uint32_t p01 = h2pack(w1[(size_t)(k4 * 4 + 0) * C3_ + n],
                              w1[(size_t)(k4 * 4 + 1) * C3_ + n]);
        uint32_t p23 = h2pack(w1[(size_t)(k4 * 4 + 2) * C3_ + n],
                              w1[(size_t)(k4 * 4 + 3) * C3_ + n]);
        *reinterpret_cast<uint2*>(&g_b1h[(size_t)n * C_ + k4 * 4]) =
            make_uint2(p01, p23);
        return;
    }
    i -= PREP_W1;
    if (i < PREP_W2) {
        int k4 = i / C_, n = i % C_;
        uint32_t p01 = h2pack(w2[(size_t)(k4 * 4 + 0) * C_ + n],
                              w2[(size_t)(k4 * 4 + 1) * C_ + n]);
        uint32_t p23 = h2pack(w2[(size_t)(k4 * 4 + 2) * C_ + n],
                              w2[(size_t)(k4 * 4 + 3) * C_ + n]);
        *reinterpret_cast<uint2*>(&g_b2h[(size_t)n * C_ + k4 * 4]) =
            make_uint2(p01, p23);
    }
}

// ---------------------------------------------------------------------------
// fp16 mma.sync GEMM (R15 measured-best config): CTA 128x128, 8 warps of
// 32x64, 3-stage cp.async, single sync per chunk.
// ---------------------------------------------------------------------------
#define G_SMEM_TOTAL 98304

struct GemmCore {
    float acc[2][8][4];
    int wm, wn, lane;
};

__device__ __forceinline__ void gemm_issue_chunk(
    uint32_t sbase, const __half* Ah, const __half* Bh,
    int m0, int n0, int K, int ch, int r, int c8)
{
    const uint32_t bofs = (uint32_t)((ch % 3) * 32768);
    const int kb = ch * 64;
    #pragma unroll
    for (int p = 0; p < 4; p++) {
        int rr = r + p * 32;
        uint32_t bo = (uint32_t)(rr * 128 + c8 * 16);
        uint32_t sw = bo ^ ((bo >> 3) & 0x70);
        cpa16(sbase + bofs + sw,         &Ah[(size_t)(m0 + rr) * K + kb + c8 * 8]);
        cpa16(sbase + bofs + 16384 + sw, &Bh[(size_t)(n0 + rr) * K + kb + c8 * 8]);
    }
    CP_COMMIT();
}

__device__ __forceinline__ void gemm_mainloop(
    GemmCore& gc, char* smem, const __half* Ah, const __half* Bh,
    int m0, int n0, int K, int tid)
{
    const uint32_t sbase = smem_u32(smem);
    const int lane = gc.lane;
    const int r  = tid >> 3;
    const int c8 = tid & 7;
    const int lrow = (lane & 7) + ((lane >> 3) & 1) * 8;
    const int lkc  = (lane >> 4);

    #pragma unroll
    for (int t = 0; t < 2; t++)
        #pragma unroll
        for (int g = 0; g < 8; g++)
            #pragma unroll
            for (int e = 0; e < 4; e++) gc.acc[t][g][e] = 0.f;

    const int nch = K / 64;

    gemm_issue_chunk(sbase, Ah, Bh, m0, n0, K, 0, r, c8);
    gemm_issue_chunk(sbase, Ah, Bh, m0, n0, K, 1, r, c8);

    for (int ch = 0; ch < nch; ch++) {
        if (ch + 1 < nch) CP_WAIT1(); else CP_WAIT0();
        __syncthreads();   // chunk ch visible; compute(ch-1) done in all warps
        if (ch + 2 < nch)
            gemm_issue_chunk(sbase, Ah, Bh, m0, n0, K, ch + 2, r, c8);

        const uint32_t sA = sbase + (uint32_t)((ch % 3) * 32768);
        const uint32_t sB = sA + 16384;

        #pragma unroll
        for (int ks = 0; ks < 4; ks++) {
            const int cc = ks * 2 + lkc;
            uint32_t a[2][4];
            #pragma unroll
            for (int t = 0; t < 2; t++) {
                int row = gc.wm * 32 + t * 16 + lrow;
                uint32_t bo = (uint32_t)(row * 128 + cc * 16);
                uint32_t sw = bo ^ ((bo >> 3) & 0x70);
                ldsm4(a[t][0], a[t][1], a[t][2], a[t][3], sA + sw);
            }
            uint32_t bf[4][4];
            #pragma unroll
            for (int g4 = 0; g4 < 4; g4++) {
                int row = gc.wn * 64 + g4 * 16 + lrow;
                uint32_t bo = (uint32_t)(row * 128 + cc * 16);
                uint32_t sw = bo ^ ((bo >> 3) & 0x70);
                ldsm4(bf[g4][0], bf[g4][1], bf[g4][2], bf[g4][3], sB + sw);
            }
            #pragma unroll
            for (int g4 = 0; g4 < 4; g4++) {
                mma_hf(gc.acc[0][g4 * 2 + 0], a[0], bf[g4][0], bf[g4][2]);
                mma_hf(gc.acc[1][g4 * 2 + 0], a[1], bf[g4][0], bf[g4][2]);
                mma_hf(gc.acc[0][g4 * 2 + 1], a[0], bf[g4][1], bf[g4][3]);
                mma_hf(gc.acc[1][g4 * 2 + 1], a[1], bf[g4][1], bf[g4][3]);
            }
        }
    }
}

// GEMM2: out = y @ w_proj + bias, fp32 output
__global__ __launch_bounds__(256, 2) void mma_gemm_out(
    const __half* __restrict__ Ah, const __half* __restrict__ Bh,
    const float* __restrict__ bias, float* __restrict__ Cm, int N)
{
    extern __shared__ char smem[];
    const int tid = threadIdx.x;
    GemmCore gc; gc.wm = (tid >> 5) & 3; gc.wn = tid >> 7; gc.lane = tid & 31;
    const int n0 = blockIdx.x * 128;
    const int m0 = blockIdx.y * 128;
    gemm_mainloop(gc, smem, Ah, Bh, m0, n0, C_, tid);

    const int crow = gc.lane >> 2;
    const int ccol = (gc.lane & 3) * 2;
    #pragma unroll
    for (int t = 0; t < 2; t++) {
        #pragma unroll
        for (int g = 0; g < 8; g++) {
            int row = m0 + gc.wm * 32 + t * 16 + crow;
            int col = n0 + gc.wn * 64 + g * 8 + ccol;
            float2 bv = *reinterpret_cast<const float2*>(&bias[col]);
            float2 o0, o1;
            o0.x = gc.acc[t][g][0] + bv.x; o0.y = gc.acc[t][g][1] + bv.y;
            o1.x = gc.acc[t][g][2] + bv.x; o1.y = gc.acc[t][g][3] + bv.y;
            *reinterpret_cast<float2*>(&Cm[(size_t)row * N + col]) = o0;
            *reinterpret_cast<float2*>(&Cm[(size_t)(row + 8) * N + col]) = o1;
        }
    }
}

// GEMM1: writes fp16 qkv per-head (q pre-scaled by 0.125*log2e)
__global__ __launch_bounds__(256, 2) void mma_gemm_qkv(
    const __half* __restrict__ Ah, const __half* __restrict__ Bh,
    const float* __restrict__ bias)
{
    extern __shared__ char smem[];
    const int tid = threadIdx.x;
    GemmCore gc; gc.wm = (tid >> 5) & 3; gc.wn = tid >> 7; gc.lane = tid & 31;
    const int n0 = blockIdx.x * 128;
    const int m0 = blockIdx.y * 128;
    gemm_mainloop(gc, smem, Ah, Bh, m0, n0, C_, tid);

    const int crow = gc.lane >> 2;
    const int ccol = (gc.lane & 3) * 2;
    #pragma unroll
    for (int t = 0; t < 2; t++) {
        #pragma unroll
        for (int g = 0; g < 8; g++) {
            int row = m0 + gc.wm * 32 + t * 16 + crow;
            int col = n0 + gc.wn * 64 + g * 8 + ccol;
            int which = col / 768, hh = (col % 768) / 64, dd = col % 64;
            int bb = row >> 12, tt = row & 4095;
            float2 bv = *reinterpret_cast<const float2*>(&bias[col]);
            float sc_ = (which == 0) ? QSCALE : 1.f;
            float v0 = (gc.acc[t][g][0] + bv.x) * sc_;
            float v1 = (gc.acc[t][g][1] + bv.y) * sc_;
            float v2 = (gc.acc[t][g][2] + bv.x) * sc_;
            float v3 = (gc.acc[t][g][3] + bv.y) * sc_;
            size_t base = (((size_t)bb * 3 + which) * NH_ + hh) * (size_t)T_ * HD_
                        + (size_t)tt * HD_ + dd;
            *reinterpret_cast<uint32_t*>(&g_qkvs[base]) = h2pack(v0, v1);
            *reinterpret_cast<uint32_t*>(&g_qkvs[base + (size_t)8 * HD_]) = h2pack(v2, v3);
        }
    }
}

// ---------------------------------------------------------------------------
// Flash attention v12 (R15, unchanged): f16-accum S, no-max softmax,
// row-sum via ones-column MMA, packed -inf causal mask.
// 4 warps x 32q, 128 q-rows/CTA. smem 48KB.
// ---------------------------------------------------------------------------
#define FL_SMEM_BYTES 49152
#define FQ_OFF 32768

__global__ __launch_bounds__(128, 3) void flash_kernel()
{
    extern __shared__ char fsm[];
    const uint32_t sb = smem_u32(fsm);

    const int tid  = threadIdx.x;
    const int w    = tid >> 5;
    const int lane = tid & 31;
    const int qt   = (gridDim.x - 1) - blockIdx.x;   // heavy tiles first
    const int h    = blockIdx.y;
    const int b    = blockIdx.z;
    const int q0   = qt * 128;

    const int lrow = (lane & 7) + ((lane >> 3) & 1) * 8;
    const int lkc  = lane >> 4;

    // ones B-fragment for row-sum MMA: col 0 only (lanes 0-3), all k = 1.0
    const uint32_t vb1 = (lane < 4) ? 0x3C003C00u : 0u;

    // K/V cp.async: 2 tiles (K,V), 64 threads each
    const int tt  = tid >> 6;            // 0=K, 1=V
    const int ll  = tid & 63;
    const int kc8 = ll & 7;
    const int kr8 = ll >> 3;             // 0..7
    const __half* kvsrc = g_qkvs +
        (((size_t)b * 3 + 1 + tt) * NH_ + h) * (size_t)T_ * HD_;
    const uint32_t kvdst = sb + tt * 8192;

    const int ktmax = 2 * qt + 2;

    // prologue: kt=0 -> buf0
    #pragma unroll
    for (int p = 0; p < 8; p++) {
        int rr = p * 8 + kr8;
        uint32_t sw = (uint32_t)(rr * 128 + ((kc8 ^ (rr & 7)) * 16));
        cpa16(kvdst + sw, &kvsrc[(size_t)rr * HD_ + kc8 * 8]);
    }
    CP_COMMIT();

    // stage Q (fp16, pre-scaled) into persistent region
    {
        const int c8  = tid & 7;
        const int r16 = tid >> 3;        // 0..15
        const __half* qsrc = g_qkvs +
            (((size_t)b * 3 + 0) * NH_ + h) * (size_t)T_ * HD_;
        #pragma unroll
        for (int p = 0; p < 8; p++) {
            int rr = p * 16 + r16;
            uint32_t sw = (uint32_t)(rr * 128 + ((c8 ^ (rr & 7)) * 16));
            *reinterpret_cast<float4*>(fsm + FQ_OFF + sw) =
                *reinterpret_cast<const float4*>(&qsrc[(size_t)(q0 + rr) * HD_ + c8 * 8]);
        }
    }
    __syncthreads();

    // preload Q fragments: qf[t][ks]
    uint32_t qf[2][4][4];
    #pragma unroll
    for (int t = 0; t < 2; t++) {
        #pragma unroll
        for (int ks = 0; ks < 4; ks++) {
            int row = w * 32 + t * 16 + lrow;
            int cc = ks * 2 + lkc;
            uint32_t sw = (uint32_t)(FQ_OFF + row * 128 + ((cc ^ (row & 7)) * 16));
            uint32_t* q = qf[t][ks];
            ldsm4(q[0], q[1], q[2], q[3], sb + sw);
        }
    }

    float oc[2][8][4];
    float ol[2][4];   // l accumulators (col 0 of ones-MMA)
    #pragma unroll
    for (int t = 0; t < 2; t++) {
        #pragma unroll
        for (int g = 0; g < 8; g++)
            #pragma unroll
            for (int e = 0; e < 4; e++) oc[t][g][e] = 0.f;
        #pragma unroll
        for (int e = 0; e < 4; e++) ol[t][e] = 0.f;
    }

    for (int kt = 0; kt < ktmax; kt++) {
        CP_WAIT0();
        __syncthreads();   // tile kt visible; compute(kt-1) done in all warps
        if (kt + 1 < ktmax) {
            const uint32_t bofs = (uint32_t)(((kt + 1) & 1) * 16384);
            #pragma unroll
            for (int p = 0; p < 8; p++) {
                int rr = p * 8 + kr8;
                uint32_t sw = (uint32_t)(rr * 128 + ((kc8 ^ (rr & 7)) * 16));
                cpa16(kvdst + bofs + sw,
                      &kvsrc[(size_t)((kt + 1) * 64 + rr) * HD_ + kc8 * 8]);
            }
            CP_COMMIT();
        }

        const uint32_t bb_ = sb + (uint32_t)((kt & 1) * 16384);

        if (kt * 64 <= q0 + w * 32 + 31) {
            // ---- S = Q K^T (fp16 accum; C-frags are packed f16x2) ----
            uint32_t s16[2][8][2];
            #pragma unroll
            for (int t = 0; t < 2; t++)
                #pragma unroll
                for (int g = 0; g < 8; g++) {
                    s16[t][g][0] = 0u; s16[t][g][1] = 0u;
                }

            #pragma unroll
            for (int ks = 0; ks < 4; ks++) {
                const int cc = ks * 2 + lkc;
                #pragma unroll
                for (int g4 = 0; g4 < 4; g4++) {
                    int row = g4 * 16 + lrow;
                    uint32_t swz = (uint32_t)(row * 128 + ((cc ^ (row & 7)) * 16));
                    uint32_t b0, b1, b2, b3;
                    ldsm4(b0, b1, b2, b3, bb_ + swz);   // K
                    mma_h16(s16[0][2 * g4 + 0], qf[0][ks], b0, b2);
                    mma_h16(s16[0][2 * g4 + 1], qf[0][ks], b1, b3);
                    mma_h16(s16[1][2 * g4 + 0], qf[1][ks], b0, b2);
                    mma_h16(s16[1][2 * g4 + 1], qf[1][ks], b1, b3);
                }
            }

            // ---- causal mask (packed -inf adds, diagonal tiles only) ----
            if (kt * 64 + 63 > q0 + w * 32) {
                #pragma unroll
                for (int t = 0; t < 2; t++) {
                    int gr0 = q0 + w * 32 + t * 16 + (lane >> 2);
                    int gr1 = gr0 + 8;
                    #pragma unroll
                    for (int g = 0; g < 8; g++) {
                        int gc0 = kt * 64 + g * 8 + 2 * (lane & 3);
                        int gc1 = gc0 + 1;
                        uint32_t m0 = h2pack(gc0 > gr0 ? -INFINITY : 0.f,
                                             gc1 > gr0 ? -INFINITY : 0.f);
                        uint32_t m1 = h2pack(gc0 > gr1 ? -INFINITY : 0.f,
                                             gc1 > gr1 ? -INFINITY : 0.f);
                        s16[t][g][0] = hadd2_(s16[t][g][0], m0);
                        s16[t][g][1] = hadd2_(s16[t][g][1], m1);
                    }
                }
            }

            // ---- P = exp2(S) in place (packed) ----
            #pragma unroll
            for (int t = 0; t < 2; t++)
                #pragma unroll
                for (int g = 0; g < 8; g++) {
                    s16[t][g][0] = hex2(s16[t][g][0]);
                    s16[t][g][1] = hex2(s16[t][g][1]);
                }

            // ---- O += P V, l += P 1 (all on tensor pipe) ----
            #pragma unroll
            for (int j = 0; j < 4; j++) {
                uint32_t ph[2][4];
                #pragma unroll
                for (int t = 0; t < 2; t++) {
                    ph[t][0] = s16[t][2 * j][0];
                    ph[t][1] = s16[t][2 * j][1];
                    ph[t][2] = s16[t][2 * j + 1][0];
                    ph[t][3] = s16[t][2 * j + 1][1];
                }
                mma_hf(ol[0], ph[0], vb1, vb1);   // row-sum
                mma_hf(ol[1], ph[1], vb1, vb1);
                #pragma unroll
                for (int g4 = 0; g4 < 4; g4++) {
                    int row = j * 16 + lrow;
                    int cc = g4 * 2 + lkc;
                    uint32_t swz = (uint32_t)(row * 128 + ((cc ^ (row & 7)) * 16));
                    uint32_t v0, v1, v2, v3;
                    ldsm4t(v0, v1, v2, v3, bb_ + 8192 + swz);   // V
                    mma_hf(oc[0][2 * g4 + 0], ph[0], v0, v1);
                    mma_hf(oc[0][2 * g4 + 1], ph[0], v2, v3);
                    mma_hf(oc[1][2 * g4 + 0], ph[1], v0, v1);
                    mma_hf(oc[1][2 * g4 + 1], ph[1], v2, v3);
                }
            }
        }
    }

    // ---- epilogue: O / l -> fp16 rows of g_yh (l lives in quad lane 0) ----
    #pragma unroll
    for (int t = 0; t < 2; t++) {
        float l0 = __shfl_sync(0xffffffffu, ol[t][0], lane & ~3);
        float l1 = __shfl_sync(0xffffffffu, ol[t][2], lane & ~3);
        float inv0 = 1.f / l0;
        float inv1 = 1.f / l1;
        #pragma unroll
        for (int g = 0; g < 8; g++) {
            int row = q0 + w * 32 + t * 16 + (lane >> 2);
            int d0  = g * 8 + 2 * (lane & 3);
            size_t base0 = (size_t)(b * T_ + row) * C_ + h * HD_ + d0;
            *reinterpret_cast<uint32_t*>(&g_yh[base0]) =
                h2pack(oc[t][g][0] * inv0, oc[t][g][1] * inv0);
            *reinterpret_cast<uint32_t*>(&g_yh[base0 + (size_t)8 * C_]) =
                h2pack(oc[t][g][2] * inv1, oc[t][g][3] * inv1);
        }
    }
}

// ---------------------------------------------------------------------------
extern "C" void kernel_launch(void* const* d_in, const int* in_sizes, int n_in,
                              void* d_out, int out_size)
{
    const float* x      = (const float*)d_in[0];
    const float* w_attn = (const float*)d_in[1];
    const float* b_attn = (const float*)d_in[2];
    const float* w_proj = (const float*)d_in[3];
    const float* b_proj = (const float*)d_in[4];
    float* out = (float*)d_out;

    __half *xh = nullptr, *b1h = nullptr, *b2h = nullptr, *yh = nullptr;
    cudaGetSymbolAddress((void**)&xh,  g_xh);
    cudaGetSymbolAddress((void**)&b1h, g_b1h);
    cudaGetSymbolAddress((void**)&b2h, g_b2h);
    cudaGetSymbolAddress((void**)&yh,  g_yh);

    cudaFuncSetAttribute(flash_kernel,
                         cudaFuncAttributeMaxDynamicSharedMemorySize, FL_SMEM_BYTES);
    cudaFuncSetAttribute(mma_gemm_out,
                         cudaFuncAttributeMaxDynamicSharedMemorySize, G_SMEM_TOTAL);
    cudaFuncSetAttribute(mma_gemm_qkv,
                         cudaFuncAttributeMaxDynamicSharedMemorySize, G_SMEM_TOTAL);

    // 0) fused prep (one launch)
    prep_all<<<(PREP_TOTAL + 255) / 256, 256>>>(x, w_attn, w_proj);

    // 1) qkv = x @ w_attn + b_attn -> fp16 q/k/v (q scaled by 0.125*log2e)
    mma_gemm_qkv<<<dim3(C3_ / 128, M_ / 128), 256, G_SMEM_TOTAL>>>(
        xh, b1h, b_attn);

    // 2) flash attention -> g_yh
    flash_kernel<<<dim3(T_ / 128, NH_, B_), 128, FL_SMEM_BYTES>>>();

    // 3) out = y @ w_proj + b_proj
    mma_gemm_out<<<dim3(C_ / 128, M_ / 128), 256, G_SMEM_TOTAL>>>(
        yh, b2h, b_proj, out, C_);
}